// round 7
// baseline (speedup 1.0000x reference)
#include <cuda_runtime.h>
#include <cuda_fp16.h>
#include <mma.h>

using namespace nvcuda;

// ---------------------------------------------------------------------------
// GCNEncoder: 2-layer GCN, N=100000, E=1600000, 1000 node types.
// Round 6: agg1/agg2 use 16-lanes-per-row with two edges in flight per warp
// (half-warps process different edges; partial sums combined via shfl_xor 16).
// W2 fp32->fp16 conversion folded into gemm2_tc smem load. count/fill 2 edges
// per thread.
// ---------------------------------------------------------------------------

#define MAXN 100000
#define MAXE 1600000
#define MAXT 4096
#define SCAN_CHUNK 1024
#define MAXNB ((MAXN + SCAN_CHUNK - 1) / SCAN_CHUNK)

__device__ int    g_cnt[MAXN];
__device__ int    g_rowptr[MAXN + 1];
__device__ int    g_wptr[MAXN];
__device__ int    g_col[MAXE];
__device__ int    g_partials[MAXNB];
__device__ float  g_dis[MAXN];
__device__ __half g_ht[(size_t)MAXT * 128];      // h_type = emb @ W1 (fp16)
__device__ __half g_a1s[(size_t)MAXN * 128];     // dis * relu(layer1) (fp16)
__device__ __half g_h2[(size_t)(MAXN + 64) * 64]; // a1s @ W2 (fp16, padded)

// ---------------------------- CSR build -----------------------------------

__global__ void count_kernel(const int* __restrict__ dst, int e, int* __restrict__ cnt) {
    int i = blockIdx.x * blockDim.x + threadIdx.x;
    int i2 = i * 2;
    if (i2 + 1 < e) {
        int2 d = __ldg((const int2*)dst + i);
        atomicAdd(&cnt[d.x], 1);
        atomicAdd(&cnt[d.y], 1);
    } else if (i2 < e) {
        atomicAdd(&cnt[dst[i2]], 1);
    }
}

__global__ __launch_bounds__(256)
void blocksum_kernel(const int* __restrict__ cnt, int* __restrict__ partials, int n) {
    int base = blockIdx.x * SCAN_CHUNK;
    int sum = 0;
    #pragma unroll
    for (int r = 0; r < 4; r++) {
        int i = base + (int)threadIdx.x + r * 256;
        if (i < n) sum += cnt[i];
    }
    #pragma unroll
    for (int off = 16; off > 0; off >>= 1)
        sum += __shfl_down_sync(0xFFFFFFFFu, sum, off);
    __shared__ int ws[8];
    int lane = threadIdx.x & 31, wid = threadIdx.x >> 5;
    if (lane == 0) ws[wid] = sum;
    __syncthreads();
    if (threadIdx.x < 8) {
        int s = ws[threadIdx.x];
        #pragma unroll
        for (int off = 4; off > 0; off >>= 1)
            s += __shfl_down_sync(0xFFu, s, off);
        if (threadIdx.x == 0) partials[blockIdx.x] = s;
    }
}

__global__ __launch_bounds__(256)
void scan_apply_kernel(const int* __restrict__ cnt,
                       const int* __restrict__ partials,
                       int* __restrict__ rowptr,
                       int* __restrict__ wptr,
                       float* __restrict__ dis,
                       int n, int nb) {
    __shared__ int s_offset;
    __shared__ int warp_sums[8];
    int lane = threadIdx.x & 31, wid = threadIdx.x >> 5;

    {
        int p = ((int)threadIdx.x < blockIdx.x && (int)threadIdx.x < nb)
                    ? partials[threadIdx.x] : 0;
        #pragma unroll
        for (int off = 16; off > 0; off >>= 1)
            p += __shfl_down_sync(0xFFFFFFFFu, p, off);
        if (lane == 0) warp_sums[wid] = p;
        __syncthreads();
        if (threadIdx.x < 8) {
            int s = warp_sums[threadIdx.x];
            #pragma unroll
            for (int off = 4; off > 0; off >>= 1)
                s += __shfl_down_sync(0xFFu, s, off);
            if (threadIdx.x == 0) s_offset = s;
        }
        __syncthreads();
    }
    int offset = s_offset;
    __syncthreads();

    int base = blockIdx.x * SCAN_CHUNK;
    int v[4], s_incl[4];
    int run = 0;
    #pragma unroll
    for (int r = 0; r < 4; r++) {
        int i = base + (int)threadIdx.x * 4 + r;
        v[r] = (i < n) ? cnt[i] : 0;
        run += v[r];
        s_incl[r] = run;
    }
    int x = run;
    #pragma unroll
    for (int off = 1; off < 32; off <<= 1) {
        int t = __shfl_up_sync(0xFFFFFFFFu, x, off);
        if (lane >= off) x += t;
    }
    if (lane == 31) warp_sums[wid] = x;
    __syncthreads();
    if (threadIdx.x < 8) {
        int s = warp_sums[threadIdx.x];
        #pragma unroll
        for (int off = 1; off < 8; off <<= 1) {
            int t = __shfl_up_sync(0xFFu, s, off);
            if ((int)threadIdx.x >= off) s += t;
        }
        warp_sums[threadIdx.x] = s;
    }
    __syncthreads();
    int thread_excl = x - run + ((wid > 0) ? warp_sums[wid - 1] : 0);

    #pragma unroll
    for (int r = 0; r < 4; r++) {
        int i = base + (int)threadIdx.x * 4 + r;
        if (i < n) {
            int incl = offset + thread_excl + s_incl[r];
            rowptr[i + 1] = incl;
            wptr[i]       = incl - v[r];
            dis[i]        = rsqrtf((float)(v[r] + 1));
        }
    }
    if (blockIdx.x == 0 && threadIdx.x == 0) rowptr[0] = 0;
}

__global__ void fill_kernel(const int* __restrict__ src, const int* __restrict__ dst,
                            int e, int* __restrict__ wptr, int* __restrict__ colx) {
    int i = blockIdx.x * blockDim.x + threadIdx.x;
    int i2 = i * 2;
    if (i2 + 1 < e) {
        int2 s = __ldg((const int2*)src + i);
        int2 d = __ldg((const int2*)dst + i);
        int p0 = atomicAdd(&wptr[d.x], 1);
        colx[p0] = s.x;
        int p1 = atomicAdd(&wptr[d.y], 1);
        colx[p1] = s.y;
    } else if (i2 < e) {
        int p = atomicAdd(&wptr[dst[i2]], 1);
        colx[p] = src[i2];
    }
}

// ---------------------------- Type GEMM ------------------------------------

__global__ __launch_bounds__(256)
void gemm_type_kernel(const float* __restrict__ A,
                      const float* __restrict__ W,
                      __half* __restrict__ out, int n) {
    __shared__ __align__(16) float As[32][68];
    __shared__ __align__(16) float Bs[32][128];

    int tid = threadIdx.x;
    int tx = tid & 31;
    int ty = tid >> 5;
    int m0 = blockIdx.x * 64;

    float acc[8][4];
    #pragma unroll
    for (int i = 0; i < 8; i++)
        #pragma unroll
        for (int j = 0; j < 4; j++) acc[i][j] = 0.0f;

    for (int kk = 0; kk < 128; kk += 32) {
        #pragma unroll
        for (int r = 0; r < 2; r++) {
            int fi = tid + r * 256;
            int m = fi >> 3;
            int q = fi & 7;
            int row = m0 + m;
            float4 v = make_float4(0.f, 0.f, 0.f, 0.f);
            if (row < n) v = *(const float4*)(A + (size_t)row * 128 + kk + q * 4);
            As[q * 4 + 0][m] = v.x;
            As[q * 4 + 1][m] = v.y;
            As[q * 4 + 2][m] = v.z;
            As[q * 4 + 3][m] = v.w;
        }
        #pragma unroll
        for (int r = 0; r < 4; r++) {
            int fi = tid + r * 256;
            int k  = fi >> 5;
            int c4 = fi & 31;
            *(float4*)&Bs[k][c4 * 4] = *(const float4*)(W + (size_t)(kk + k) * 128 + c4 * 4);
        }
        __syncthreads();
        #pragma unroll
        for (int k = 0; k < 32; k++) {
            float4 a0 = *(const float4*)&As[k][ty * 8];
            float4 a1 = *(const float4*)&As[k][ty * 8 + 4];
            float a[8] = {a0.x, a0.y, a0.z, a0.w, a1.x, a1.y, a1.z, a1.w};
            float4 bv = *(const float4*)&Bs[k][tx * 4];
            float b[4] = {bv.x, bv.y, bv.z, bv.w};
            #pragma unroll
            for (int i = 0; i < 8; i++)
                #pragma unroll
                for (int j = 0; j < 4; j++)
                    acc[i][j] = fmaf(a[i], b[j], acc[i][j]);
        }
        __syncthreads();
    }
    #pragma unroll
    for (int i = 0; i < 8; i++) {
        int row = m0 + ty * 8 + i;
        if (row < n) {
            __half2 h0 = __floats2half2_rn(acc[i][0], acc[i][1]);
            __half2 h1 = __floats2half2_rn(acc[i][2], acc[i][3]);
            uint2 u = make_uint2(*(unsigned*)&h0, *(unsigned*)&h1);
            *(uint2*)(out + (size_t)row * 128 + tx * 4) = u;
        }
    }
}

// ---------------------------- Fused layer-1 aggregation ---------------------
// 16 lanes per 128-col row (uint4/lane); half-warps process 2 edges at once.
// a1s[w] = fp16(dis[w] * relu(dis[w]*acc + b1)).

__global__ __launch_bounds__(256)
void agg1_fused_kernel(const __half* __restrict__ ht,
                       const int* __restrict__ types,
                       const int* __restrict__ rowptr,
                       const int* __restrict__ colx,
                       const float* __restrict__ dis,
                       const float* __restrict__ bias,
                       __half* __restrict__ out, int n) {
    int w = (int)((blockIdx.x * blockDim.x + threadIdx.x) >> 5);
    int lane = threadIdx.x & 31;
    int hw = lane >> 4;       // half-warp id
    int hl = lane & 15;       // lane within half
    if (w >= n) return;

    float dd = __ldg(&dis[w]);
    int   td = __ldg(&types[w]);

    float acc[8];
    {
        // self term, lower half only (halves combined at the end)
        uint4 u = __ldg((const uint4*)(ht + (size_t)td * 128 + hl * 8));
        float s = hw ? 0.0f : dd;
        float2 f0 = __half22float2(*(__half2*)&u.x);
        float2 f1 = __half22float2(*(__half2*)&u.y);
        float2 f2 = __half22float2(*(__half2*)&u.z);
        float2 f3 = __half22float2(*(__half2*)&u.w);
        acc[0] = s * f0.x; acc[1] = s * f0.y;
        acc[2] = s * f1.x; acc[3] = s * f1.y;
        acc[4] = s * f2.x; acc[5] = s * f2.y;
        acc[6] = s * f3.x; acc[7] = s * f3.y;
    }

    int j  = __ldg(&rowptr[w]);
    int j1 = __ldg(&rowptr[w + 1]);
    while (j < j1) {
        int m = j1 - j;
        if (m > 32) m = 32;
        int t = 0;
        float ds = 0.0f;
        if (lane < m) {
            int s = __ldg(&colx[j + lane]);
            t  = __ldg(&types[s]);
            ds = __ldg(&dis[s]);
        }
        for (int b = 0; b < m; b += 2) {
            int eidx = b + hw;
            bool valid = eidx < m;
            int   tE = __shfl_sync(0xFFFFFFFFu, t,  valid ? eidx : 0);
            float dE = __shfl_sync(0xFFFFFFFFu, ds, valid ? eidx : 0);
            if (!valid) dE = 0.0f;
            uint4 u = __ldg((const uint4*)(ht + (size_t)tE * 128 + hl * 8));
            float2 f0 = __half22float2(*(__half2*)&u.x);
            float2 f1 = __half22float2(*(__half2*)&u.y);
            float2 f2 = __half22float2(*(__half2*)&u.z);
            float2 f3 = __half22float2(*(__half2*)&u.w);
            acc[0] = fmaf(dE, f0.x, acc[0]); acc[1] = fmaf(dE, f0.y, acc[1]);
            acc[2] = fmaf(dE, f1.x, acc[2]); acc[3] = fmaf(dE, f1.y, acc[3]);
            acc[4] = fmaf(dE, f2.x, acc[4]); acc[5] = fmaf(dE, f2.y, acc[5]);
            acc[6] = fmaf(dE, f3.x, acc[6]); acc[7] = fmaf(dE, f3.y, acc[7]);
        }
        j += m;
    }

    // combine half-warps
    #pragma unroll
    for (int i = 0; i < 8; i++)
        acc[i] += __shfl_xor_sync(0xFFFFFFFFu, acc[i], 16);

    if (!hw) {
        float4 b0 = __ldg((const float4*)(bias + hl * 8));
        float4 b1v = __ldg((const float4*)(bias + hl * 8 + 4));
        float r0 = dd * fmaxf(fmaf(dd, acc[0], b0.x), 0.0f);
        float r1 = dd * fmaxf(fmaf(dd, acc[1], b0.y), 0.0f);
        float r2 = dd * fmaxf(fmaf(dd, acc[2], b0.z), 0.0f);
        float r3 = dd * fmaxf(fmaf(dd, acc[3], b0.w), 0.0f);
        float r4 = dd * fmaxf(fmaf(dd, acc[4], b1v.x), 0.0f);
        float r5 = dd * fmaxf(fmaf(dd, acc[5], b1v.y), 0.0f);
        float r6 = dd * fmaxf(fmaf(dd, acc[6], b1v.z), 0.0f);
        float r7 = dd * fmaxf(fmaf(dd, acc[7], b1v.w), 0.0f);
        __half2 h0 = __floats2half2_rn(r0, r1);
        __half2 h1 = __floats2half2_rn(r2, r3);
        __half2 h2v = __floats2half2_rn(r4, r5);
        __half2 h3 = __floats2half2_rn(r6, r7);
        uint4 u = make_uint4(*(unsigned*)&h0, *(unsigned*)&h1,
                             *(unsigned*)&h2v, *(unsigned*)&h3);
        *(uint4*)(out + (size_t)w * 128 + hl * 8) = u;
    }
}

// ---------------------------- Layer-2 GEMM (tensor cores) -------------------
// h2[64 rows] = A_tile[64,128] @ W2[128,64]; W2 converted fp32->fp16 in-kernel.

__global__ __launch_bounds__(256)
void gemm2_tc_kernel(const __half* __restrict__ A,
                     const float* __restrict__ W32,
                     __half* __restrict__ out, int n) {
    __shared__ __align__(16) __half As[64][136];
    __shared__ __align__(16) __half Ws[128][72];

    int tid = threadIdx.x;
    int wid = tid >> 5;
    int m0 = blockIdx.x * 64;

    // A tile: 64 x 128 halves = 1024 uint4; 4 per thread.
    #pragma unroll
    for (int r = 0; r < 4; r++) {
        int fi = tid + r * 256;
        int m = fi >> 4;
        int q = fi & 15;
        int row = m0 + m;
        uint4 v = make_uint4(0, 0, 0, 0);
        if (row < n) v = *(const uint4*)(A + (size_t)row * 128 + q * 8);
        *(uint4*)&As[m][q * 8] = v;
    }
    // W2: 128 x 64 fp32 = 2048 float4; 8 per thread; convert to half.
    #pragma unroll
    for (int r = 0; r < 8; r++) {
        int fi = tid + r * 256;
        int k = fi >> 4;          // W row
        int q = fi & 15;          // float4 within row (16 per row)
        float4 v = __ldg((const float4*)(W32 + (size_t)k * 64 + q * 4));
        __half2 h0 = __floats2half2_rn(v.x, v.y);
        __half2 h1 = __floats2half2_rn(v.z, v.w);
        *(uint2*)&Ws[k][q * 4] = make_uint2(*(unsigned*)&h0, *(unsigned*)&h1);
    }
    __syncthreads();

    int wm = wid >> 1;
    int wn = wid & 1;

    wmma::fragment<wmma::accumulator, 16, 16, 16, float> c[2];
    wmma::fill_fragment(c[0], 0.0f);
    wmma::fill_fragment(c[1], 0.0f);

    #pragma unroll
    for (int k = 0; k < 8; k++) {
        wmma::fragment<wmma::matrix_a, 16, 16, 16, __half, wmma::row_major> af;
        wmma::load_matrix_sync(af, &As[wm * 16][k * 16], 136);
        #pragma unroll
        for (int f = 0; f < 2; f++) {
            wmma::fragment<wmma::matrix_b, 16, 16, 16, __half, wmma::row_major> bf;
            wmma::load_matrix_sync(bf, &Ws[k * 16][wn * 32 + f * 16], 72);
            wmma::mma_sync(c[f], af, bf, c[f]);
        }
    }

    #pragma unroll
    for (int f = 0; f < 2; f++) {
        wmma::fragment<wmma::accumulator, 16, 16, 16, __half> ch;
        #pragma unroll
        for (int i = 0; i < ch.num_elements; i++)
            ch.x[i] = __float2half(c[f].x[i]);
        wmma::store_matrix_sync(out + (size_t)(m0 + wm * 16) * 64 + wn * 32 + f * 16,
                                ch, 64, wmma::mem_row_major);
    }
}

// ---------------------------- Layer-2 aggregation ---------------------------
// 16 lanes per 64-col fp16 row (uint2/lane); 2 edges per warp iteration.

__global__ __launch_bounds__(256)
void agg2_kernel(const __half* __restrict__ h,
                 const int* __restrict__ rowptr,
                 const int* __restrict__ colx,
                 const float* __restrict__ dis,
                 const float* __restrict__ bias,
                 float* __restrict__ out, int n) {
    int w = (int)((blockIdx.x * blockDim.x + threadIdx.x) >> 5);
    int lane = threadIdx.x & 31;
    int hw = lane >> 4;
    int hl = lane & 15;
    if (w >= n) return;

    float acc[4];
    {
        uint2 u = __ldg((const uint2*)(h + (size_t)w * 64 + hl * 4));
        float2 f0 = __half22float2(*(__half2*)&u.x);
        float2 f1 = __half22float2(*(__half2*)&u.y);
        float s = hw ? 0.0f : 1.0f;
        acc[0] = s * f0.x; acc[1] = s * f0.y;
        acc[2] = s * f1.x; acc[3] = s * f1.y;
    }

    int j  = __ldg(&rowptr[w]);
    int j1 = __ldg(&rowptr[w + 1]);
    while (j < j1) {
        int m = j1 - j;
        if (m > 32) m = 32;
        int s0 = 0;
        if (lane < m) s0 = __ldg(&colx[j + lane]);
        for (int b = 0; b < m; b += 2) {
            int eidx = b + hw;
            bool valid = eidx < m;
            int sE = __shfl_sync(0xFFFFFFFFu, s0, valid ? eidx : 0);
            uint2 u = __ldg((const uint2*)(h + (size_t)sE * 64 + hl * 4));
            float2 f0 = __half22float2(*(__half2*)&u.x);
            float2 f1 = __half22float2(*(__half2*)&u.y);
            if (valid) {
                acc[0] += f0.x; acc[1] += f0.y;
                acc[2] += f1.x; acc[3] += f1.y;
            }
        }
        j += m;
    }

    #pragma unroll
    for (int i = 0; i < 4; i++)
        acc[i] += __shfl_xor_sync(0xFFFFFFFFu, acc[i], 16);

    if (!hw) {
        float sc = __ldg(&dis[w]);
        float4 bb = __ldg((const float4*)(bias + hl * 4));
        float4 res = make_float4(fmaf(sc, acc[0], bb.x), fmaf(sc, acc[1], bb.y),
                                 fmaf(sc, acc[2], bb.z), fmaf(sc, acc[3], bb.w));
        *(float4*)(out + (size_t)w * 64 + hl * 4) = res;
    }
}

// ---------------------------- Launch ----------------------------------------

extern "C" void kernel_launch(void* const* d_in, const int* in_sizes, int n_in,
                              void* d_out, int out_size) {
    const int*   types = (const int*)d_in[0];
    const int*   ei    = (const int*)d_in[1];
    const float* emb   = (const float*)d_in[2];
    const float* W1    = (const float*)d_in[3];
    const float* b1    = (const float*)d_in[4];
    const float* W2    = (const float*)d_in[5];
    const float* b2    = (const float*)d_in[6];
    float* out = (float*)d_out;

    int n  = in_sizes[0];
    int e  = in_sizes[1] / 2;
    int nt = in_sizes[2] / 128;
    if (n > MAXN) n = MAXN;
    if (e > MAXE) e = MAXE;
    if (nt > MAXT) nt = MAXT;
    const int* src = ei;
    const int* dst = ei + e;

    int *cnt, *rowptr, *wptr, *colx, *partials;
    float *dis;
    __half *ht, *a1s, *h2;
    cudaGetSymbolAddress((void**)&cnt,      g_cnt);
    cudaGetSymbolAddress((void**)&rowptr,   g_rowptr);
    cudaGetSymbolAddress((void**)&wptr,     g_wptr);
    cudaGetSymbolAddress((void**)&colx,     g_col);
    cudaGetSymbolAddress((void**)&partials, g_partials);
    cudaGetSymbolAddress((void**)&dis,      g_dis);
    cudaGetSymbolAddress((void**)&ht,       g_ht);
    cudaGetSymbolAddress((void**)&a1s,      g_a1s);
    cudaGetSymbolAddress((void**)&h2,       g_h2);

    int nb   = (n + SCAN_CHUNK - 1) / SCAN_CHUNK;
    int nb_e2 = (e / 2 + 256) / 256;   // 2 edges per thread (covers tail)

    gemm_type_kernel<<<(nt + 63) / 64, 256>>>(emb, W1, ht, nt);

    cudaMemsetAsync(cnt, 0, (size_t)n * sizeof(int));
    count_kernel<<<nb_e2, 256>>>(dst, e, cnt);
    blocksum_kernel<<<nb, 256>>>(cnt, partials, n);
    scan_apply_kernel<<<nb, 256>>>(cnt, partials, rowptr, wptr, dis, n, nb);
    fill_kernel<<<nb_e2, 256>>>(src, dst, e, wptr, colx);

    int agg_blocks = (n + 7) / 8;

    agg1_fused_kernel<<<agg_blocks, 256>>>(ht, types, rowptr, colx, dis, b1, a1s, n);

    gemm2_tc_kernel<<<(n + 63) / 64, 256>>>(a1s, W2, h2, n);
    agg2_kernel<<<agg_blocks, 256>>>(h2, rowptr, colx, dis, b2, out, n);
}

// round 8
// speedup vs baseline: 1.0681x; 1.0681x over previous
#include <cuda_runtime.h>
#include <cuda_fp16.h>
#include <mma.h>

using namespace nvcuda;

// ---------------------------------------------------------------------------
// GCNEncoder: 2-layer GCN, N=100000, E=1600000, 1000 node types.
// Round 7: revert aggs to round-5 lane layout (half-warp scheme regressed);
// unroll inner edge loop x4 for 4 independent gathers in flight (latency
// hiding). Keep vectorized count/fill and in-kernel W2 conversion.
// ---------------------------------------------------------------------------

#define MAXN 100000
#define MAXE 1600000
#define MAXT 4096
#define SCAN_CHUNK 1024
#define MAXNB ((MAXN + SCAN_CHUNK - 1) / SCAN_CHUNK)

__device__ int    g_cnt[MAXN];
__device__ int    g_rowptr[MAXN + 1];
__device__ int    g_wptr[MAXN];
__device__ int    g_col[MAXE];
__device__ int    g_partials[MAXNB];
__device__ float  g_dis[MAXN];
__device__ __half g_ht[(size_t)MAXT * 128];       // h_type = emb @ W1 (fp16)
__device__ __half g_a1s[(size_t)MAXN * 128];      // dis * relu(layer1) (fp16)
__device__ __half g_h2[(size_t)(MAXN + 64) * 64]; // a1s @ W2 (fp16, padded)

// ---------------------------- CSR build -----------------------------------

__global__ void count_kernel(const int* __restrict__ dst, int e, int* __restrict__ cnt) {
    int i = blockIdx.x * blockDim.x + threadIdx.x;
    int i2 = i * 2;
    if (i2 + 1 < e) {
        int2 d = __ldg((const int2*)dst + i);
        atomicAdd(&cnt[d.x], 1);
        atomicAdd(&cnt[d.y], 1);
    } else if (i2 < e) {
        atomicAdd(&cnt[dst[i2]], 1);
    }
}

__global__ __launch_bounds__(256)
void blocksum_kernel(const int* __restrict__ cnt, int* __restrict__ partials, int n) {
    int base = blockIdx.x * SCAN_CHUNK;
    int sum = 0;
    #pragma unroll
    for (int r = 0; r < 4; r++) {
        int i = base + (int)threadIdx.x + r * 256;
        if (i < n) sum += cnt[i];
    }
    #pragma unroll
    for (int off = 16; off > 0; off >>= 1)
        sum += __shfl_down_sync(0xFFFFFFFFu, sum, off);
    __shared__ int ws[8];
    int lane = threadIdx.x & 31, wid = threadIdx.x >> 5;
    if (lane == 0) ws[wid] = sum;
    __syncthreads();
    if (threadIdx.x < 8) {
        int s = ws[threadIdx.x];
        #pragma unroll
        for (int off = 4; off > 0; off >>= 1)
            s += __shfl_down_sync(0xFFu, s, off);
        if (threadIdx.x == 0) partials[blockIdx.x] = s;
    }
}

__global__ __launch_bounds__(256)
void scan_apply_kernel(const int* __restrict__ cnt,
                       const int* __restrict__ partials,
                       int* __restrict__ rowptr,
                       int* __restrict__ wptr,
                       float* __restrict__ dis,
                       int n, int nb) {
    __shared__ int s_offset;
    __shared__ int warp_sums[8];
    int lane = threadIdx.x & 31, wid = threadIdx.x >> 5;

    {
        int p = ((int)threadIdx.x < blockIdx.x && (int)threadIdx.x < nb)
                    ? partials[threadIdx.x] : 0;
        #pragma unroll
        for (int off = 16; off > 0; off >>= 1)
            p += __shfl_down_sync(0xFFFFFFFFu, p, off);
        if (lane == 0) warp_sums[wid] = p;
        __syncthreads();
        if (threadIdx.x < 8) {
            int s = warp_sums[threadIdx.x];
            #pragma unroll
            for (int off = 4; off > 0; off >>= 1)
                s += __shfl_down_sync(0xFFu, s, off);
            if (threadIdx.x == 0) s_offset = s;
        }
        __syncthreads();
    }
    int offset = s_offset;
    __syncthreads();

    int base = blockIdx.x * SCAN_CHUNK;
    int v[4], s_incl[4];
    int run = 0;
    #pragma unroll
    for (int r = 0; r < 4; r++) {
        int i = base + (int)threadIdx.x * 4 + r;
        v[r] = (i < n) ? cnt[i] : 0;
        run += v[r];
        s_incl[r] = run;
    }
    int x = run;
    #pragma unroll
    for (int off = 1; off < 32; off <<= 1) {
        int t = __shfl_up_sync(0xFFFFFFFFu, x, off);
        if (lane >= off) x += t;
    }
    if (lane == 31) warp_sums[wid] = x;
    __syncthreads();
    if (threadIdx.x < 8) {
        int s = warp_sums[threadIdx.x];
        #pragma unroll
        for (int off = 1; off < 8; off <<= 1) {
            int t = __shfl_up_sync(0xFFu, s, off);
            if ((int)threadIdx.x >= off) s += t;
        }
        warp_sums[threadIdx.x] = s;
    }
    __syncthreads();
    int thread_excl = x - run + ((wid > 0) ? warp_sums[wid - 1] : 0);

    #pragma unroll
    for (int r = 0; r < 4; r++) {
        int i = base + (int)threadIdx.x * 4 + r;
        if (i < n) {
            int incl = offset + thread_excl + s_incl[r];
            rowptr[i + 1] = incl;
            wptr[i]       = incl - v[r];
            dis[i]        = rsqrtf((float)(v[r] + 1));
        }
    }
    if (blockIdx.x == 0 && threadIdx.x == 0) rowptr[0] = 0;
}

__global__ void fill_kernel(const int* __restrict__ src, const int* __restrict__ dst,
                            int e, int* __restrict__ wptr, int* __restrict__ colx) {
    int i = blockIdx.x * blockDim.x + threadIdx.x;
    int i2 = i * 2;
    if (i2 + 1 < e) {
        int2 s = __ldg((const int2*)src + i);
        int2 d = __ldg((const int2*)dst + i);
        int p0 = atomicAdd(&wptr[d.x], 1);
        colx[p0] = s.x;
        int p1 = atomicAdd(&wptr[d.y], 1);
        colx[p1] = s.y;
    } else if (i2 < e) {
        int p = atomicAdd(&wptr[dst[i2]], 1);
        colx[p] = src[i2];
    }
}

// ---------------------------- Type GEMM ------------------------------------

__global__ __launch_bounds__(256)
void gemm_type_kernel(const float* __restrict__ A,
                      const float* __restrict__ W,
                      __half* __restrict__ out, int n) {
    __shared__ __align__(16) float As[32][68];
    __shared__ __align__(16) float Bs[32][128];

    int tid = threadIdx.x;
    int tx = tid & 31;
    int ty = tid >> 5;
    int m0 = blockIdx.x * 64;

    float acc[8][4];
    #pragma unroll
    for (int i = 0; i < 8; i++)
        #pragma unroll
        for (int j = 0; j < 4; j++) acc[i][j] = 0.0f;

    for (int kk = 0; kk < 128; kk += 32) {
        #pragma unroll
        for (int r = 0; r < 2; r++) {
            int fi = tid + r * 256;
            int m = fi >> 3;
            int q = fi & 7;
            int row = m0 + m;
            float4 v = make_float4(0.f, 0.f, 0.f, 0.f);
            if (row < n) v = *(const float4*)(A + (size_t)row * 128 + kk + q * 4);
            As[q * 4 + 0][m] = v.x;
            As[q * 4 + 1][m] = v.y;
            As[q * 4 + 2][m] = v.z;
            As[q * 4 + 3][m] = v.w;
        }
        #pragma unroll
        for (int r = 0; r < 4; r++) {
            int fi = tid + r * 256;
            int k  = fi >> 5;
            int c4 = fi & 31;
            *(float4*)&Bs[k][c4 * 4] = *(const float4*)(W + (size_t)(kk + k) * 128 + c4 * 4);
        }
        __syncthreads();
        #pragma unroll
        for (int k = 0; k < 32; k++) {
            float4 a0 = *(const float4*)&As[k][ty * 8];
            float4 a1 = *(const float4*)&As[k][ty * 8 + 4];
            float a[8] = {a0.x, a0.y, a0.z, a0.w, a1.x, a1.y, a1.z, a1.w};
            float4 bv = *(const float4*)&Bs[k][tx * 4];
            float b[4] = {bv.x, bv.y, bv.z, bv.w};
            #pragma unroll
            for (int i = 0; i < 8; i++)
                #pragma unroll
                for (int j = 0; j < 4; j++)
                    acc[i][j] = fmaf(a[i], b[j], acc[i][j]);
        }
        __syncthreads();
    }
    #pragma unroll
    for (int i = 0; i < 8; i++) {
        int row = m0 + ty * 8 + i;
        if (row < n) {
            __half2 h0 = __floats2half2_rn(acc[i][0], acc[i][1]);
            __half2 h1 = __floats2half2_rn(acc[i][2], acc[i][3]);
            uint2 u = make_uint2(*(unsigned*)&h0, *(unsigned*)&h1);
            *(uint2*)(out + (size_t)row * 128 + tx * 4) = u;
        }
    }
}

// ---------------------------- Fused layer-1 aggregation ---------------------
// One warp per dst node, 32 lanes x uint2 (4 cols) per ht row. Inner edge
// loop unrolled x4: 4 independent gathers in flight per warp.

__global__ __launch_bounds__(256)
void agg1_fused_kernel(const __half* __restrict__ ht,
                       const int* __restrict__ types,
                       const int* __restrict__ rowptr,
                       const int* __restrict__ colx,
                       const float* __restrict__ dis,
                       const float* __restrict__ bias,
                       __half* __restrict__ out, int n) {
    int w = (int)((blockIdx.x * blockDim.x + threadIdx.x) >> 5);
    int lane = threadIdx.x & 31;
    if (w >= n) return;

    float dd = __ldg(&dis[w]);
    int   td = __ldg(&types[w]);
    float ax, ay, az, aw;
    {
        uint2 u = __ldg((const uint2*)(ht + (size_t)td * 128) + lane);
        float2 f0 = __half22float2(*(__half2*)&u.x);
        float2 f1 = __half22float2(*(__half2*)&u.y);
        ax = dd * f0.x; ay = dd * f0.y; az = dd * f1.x; aw = dd * f1.y;
    }

    int j  = __ldg(&rowptr[w]);
    int j1 = __ldg(&rowptr[w + 1]);
    while (j < j1) {
        int m = j1 - j;
        if (m > 32) m = 32;
        int t = 0;
        float ds = 0.0f;
        if (lane < m) {
            int s = __ldg(&colx[j + lane]);
            t  = __ldg(&types[s]);
            ds = __ldg(&dis[s]);
        }
        int b = 0;
        for (; b + 3 < m; b += 4) {
            int   t0 = __shfl_sync(0xFFFFFFFFu, t,  b);
            float d0 = __shfl_sync(0xFFFFFFFFu, ds, b);
            int   t1 = __shfl_sync(0xFFFFFFFFu, t,  b + 1);
            float d1 = __shfl_sync(0xFFFFFFFFu, ds, b + 1);
            int   t2 = __shfl_sync(0xFFFFFFFFu, t,  b + 2);
            float d2 = __shfl_sync(0xFFFFFFFFu, ds, b + 2);
            int   t3 = __shfl_sync(0xFFFFFFFFu, t,  b + 3);
            float d3 = __shfl_sync(0xFFFFFFFFu, ds, b + 3);
            uint2 u0 = __ldg((const uint2*)(ht + (size_t)t0 * 128) + lane);
            uint2 u1 = __ldg((const uint2*)(ht + (size_t)t1 * 128) + lane);
            uint2 u2 = __ldg((const uint2*)(ht + (size_t)t2 * 128) + lane);
            uint2 u3 = __ldg((const uint2*)(ht + (size_t)t3 * 128) + lane);
            float2 p0 = __half22float2(*(__half2*)&u0.x);
            float2 q0 = __half22float2(*(__half2*)&u0.y);
            float2 p1 = __half22float2(*(__half2*)&u1.x);
            float2 q1 = __half22float2(*(__half2*)&u1.y);
            float2 p2 = __half22float2(*(__half2*)&u2.x);
            float2 q2 = __half22float2(*(__half2*)&u2.y);
            float2 p3 = __half22float2(*(__half2*)&u3.x);
            float2 q3 = __half22float2(*(__half2*)&u3.y);
            ax = fmaf(d0, p0.x, ax); ay = fmaf(d0, p0.y, ay);
            az = fmaf(d0, q0.x, az); aw = fmaf(d0, q0.y, aw);
            ax = fmaf(d1, p1.x, ax); ay = fmaf(d1, p1.y, ay);
            az = fmaf(d1, q1.x, az); aw = fmaf(d1, q1.y, aw);
            ax = fmaf(d2, p2.x, ax); ay = fmaf(d2, p2.y, ay);
            az = fmaf(d2, q2.x, az); aw = fmaf(d2, q2.y, aw);
            ax = fmaf(d3, p3.x, ax); ay = fmaf(d3, p3.y, ay);
            az = fmaf(d3, q3.x, az); aw = fmaf(d3, q3.y, aw);
        }
        for (; b < m; b++) {
            int   tA = __shfl_sync(0xFFFFFFFFu, t,  b);
            float dA = __shfl_sync(0xFFFFFFFFu, ds, b);
            uint2 uA = __ldg((const uint2*)(ht + (size_t)tA * 128) + lane);
            float2 a0 = __half22float2(*(__half2*)&uA.x);
            float2 a1 = __half22float2(*(__half2*)&uA.y);
            ax = fmaf(dA, a0.x, ax); ay = fmaf(dA, a0.y, ay);
            az = fmaf(dA, a1.x, az); aw = fmaf(dA, a1.y, aw);
        }
        j += m;
    }

    float4 bb = __ldg((const float4*)bias + lane);
    // r = relu(dd*acc + b); store dd*r (layer-2 source prescale folded in)
    float r0 = dd * fmaxf(fmaf(dd, ax, bb.x), 0.0f);
    float r1 = dd * fmaxf(fmaf(dd, ay, bb.y), 0.0f);
    float r2 = dd * fmaxf(fmaf(dd, az, bb.z), 0.0f);
    float r3 = dd * fmaxf(fmaf(dd, aw, bb.w), 0.0f);
    __half2 h0 = __floats2half2_rn(r0, r1);
    __half2 h1 = __floats2half2_rn(r2, r3);
    uint2 u = make_uint2(*(unsigned*)&h0, *(unsigned*)&h1);
    ((uint2*)(out + (size_t)w * 128))[lane] = u;
}

// ---------------------------- Layer-2 GEMM (tensor cores) -------------------
// h2[64 rows] = A_tile[64,128] @ W2[128,64]; W2 converted fp32->fp16 in-kernel.

__global__ __launch_bounds__(256)
void gemm2_tc_kernel(const __half* __restrict__ A,
                     const float* __restrict__ W32,
                     __half* __restrict__ out, int n) {
    __shared__ __align__(16) __half As[64][136];
    __shared__ __align__(16) __half Ws[128][72];

    int tid = threadIdx.x;
    int wid = tid >> 5;
    int m0 = blockIdx.x * 64;

    #pragma unroll
    for (int r = 0; r < 4; r++) {
        int fi = tid + r * 256;
        int m = fi >> 4;
        int q = fi & 15;
        int row = m0 + m;
        uint4 v = make_uint4(0, 0, 0, 0);
        if (row < n) v = *(const uint4*)(A + (size_t)row * 128 + q * 8);
        *(uint4*)&As[m][q * 8] = v;
    }
    #pragma unroll
    for (int r = 0; r < 8; r++) {
        int fi = tid + r * 256;
        int k = fi >> 4;
        int q = fi & 15;
        float4 v = __ldg((const float4*)(W32 + (size_t)k * 64 + q * 4));
        __half2 h0 = __floats2half2_rn(v.x, v.y);
        __half2 h1 = __floats2half2_rn(v.z, v.w);
        *(uint2*)&Ws[k][q * 4] = make_uint2(*(unsigned*)&h0, *(unsigned*)&h1);
    }
    __syncthreads();

    int wm = wid >> 1;
    int wn = wid & 1;

    wmma::fragment<wmma::accumulator, 16, 16, 16, float> c[2];
    wmma::fill_fragment(c[0], 0.0f);
    wmma::fill_fragment(c[1], 0.0f);

    #pragma unroll
    for (int k = 0; k < 8; k++) {
        wmma::fragment<wmma::matrix_a, 16, 16, 16, __half, wmma::row_major> af;
        wmma::load_matrix_sync(af, &As[wm * 16][k * 16], 136);
        #pragma unroll
        for (int f = 0; f < 2; f++) {
            wmma::fragment<wmma::matrix_b, 16, 16, 16, __half, wmma::row_major> bf;
            wmma::load_matrix_sync(bf, &Ws[k * 16][wn * 32 + f * 16], 72);
            wmma::mma_sync(c[f], af, bf, c[f]);
        }
    }

    #pragma unroll
    for (int f = 0; f < 2; f++) {
        wmma::fragment<wmma::accumulator, 16, 16, 16, __half> ch;
        #pragma unroll
        for (int i = 0; i < ch.num_elements; i++)
            ch.x[i] = __float2half(c[f].x[i]);
        wmma::store_matrix_sync(out + (size_t)(m0 + wm * 16) * 64 + wn * 32 + f * 16,
                                ch, 64, wmma::mem_row_major);
    }
}

// ---------------------------- Layer-2 aggregation ---------------------------
// One warp per dst node, 32 lanes x u32 (2 cols) per h2 row. Unroll x4.

__global__ __launch_bounds__(256)
void agg2_kernel(const __half* __restrict__ h,
                 const int* __restrict__ rowptr,
                 const int* __restrict__ colx,
                 const float* __restrict__ dis,
                 const float* __restrict__ bias,
                 float* __restrict__ out, int n) {
    int w = (int)((blockIdx.x * blockDim.x + threadIdx.x) >> 5);
    int lane = threadIdx.x & 31;
    if (w >= n) return;

    float2 acc;
    {
        unsigned u = __ldg((const unsigned*)(h + (size_t)w * 64) + lane);
        acc = __half22float2(*(__half2*)&u);
    }
    int j  = __ldg(&rowptr[w]);
    int j1 = __ldg(&rowptr[w + 1]);
    while (j < j1) {
        int m = j1 - j;
        if (m > 32) m = 32;
        int s0 = 0;
        if (lane < m) s0 = __ldg(&colx[j + lane]);
        int b = 0;
        for (; b + 3 < m; b += 4) {
            int e0 = __shfl_sync(0xFFFFFFFFu, s0, b);
            int e1 = __shfl_sync(0xFFFFFFFFu, s0, b + 1);
            int e2 = __shfl_sync(0xFFFFFFFFu, s0, b + 2);
            int e3 = __shfl_sync(0xFFFFFFFFu, s0, b + 3);
            unsigned u0 = __ldg((const unsigned*)(h + (size_t)e0 * 64) + lane);
            unsigned u1 = __ldg((const unsigned*)(h + (size_t)e1 * 64) + lane);
            unsigned u2 = __ldg((const unsigned*)(h + (size_t)e2 * 64) + lane);
            unsigned u3 = __ldg((const unsigned*)(h + (size_t)e3 * 64) + lane);
            float2 f0 = __half22float2(*(__half2*)&u0);
            float2 f1 = __half22float2(*(__half2*)&u1);
            float2 f2 = __half22float2(*(__half2*)&u2);
            float2 f3 = __half22float2(*(__half2*)&u3);
            acc.x += (f0.x + f1.x) + (f2.x + f3.x);
            acc.y += (f0.y + f1.y) + (f2.y + f3.y);
        }
        for (; b < m; b++) {
            int eA = __shfl_sync(0xFFFFFFFFu, s0, b);
            unsigned u = __ldg((const unsigned*)(h + (size_t)eA * 64) + lane);
            float2 v = __half22float2(*(__half2*)&u);
            acc.x += v.x;
            acc.y += v.y;
        }
        j += m;
    }
    float sc = __ldg(&dis[w]);
    float2 bb = *(const float2*)(bias + lane * 2);
    *(float2*)(out + (size_t)w * 64 + lane * 2) =
        make_float2(fmaf(sc, acc.x, bb.x), fmaf(sc, acc.y, bb.y));
}

// ---------------------------- Launch ----------------------------------------

extern "C" void kernel_launch(void* const* d_in, const int* in_sizes, int n_in,
                              void* d_out, int out_size) {
    const int*   types = (const int*)d_in[0];
    const int*   ei    = (const int*)d_in[1];
    const float* emb   = (const float*)d_in[2];
    const float* W1    = (const float*)d_in[3];
    const float* b1    = (const float*)d_in[4];
    const float* W2    = (const float*)d_in[5];
    const float* b2    = (const float*)d_in[6];
    float* out = (float*)d_out;

    int n  = in_sizes[0];
    int e  = in_sizes[1] / 2;
    int nt = in_sizes[2] / 128;
    if (n > MAXN) n = MAXN;
    if (e > MAXE) e = MAXE;
    if (nt > MAXT) nt = MAXT;
    const int* src = ei;
    const int* dst = ei + e;

    int *cnt, *rowptr, *wptr, *colx, *partials;
    float *dis;
    __half *ht, *a1s, *h2;
    cudaGetSymbolAddress((void**)&cnt,      g_cnt);
    cudaGetSymbolAddress((void**)&rowptr,   g_rowptr);
    cudaGetSymbolAddress((void**)&wptr,     g_wptr);
    cudaGetSymbolAddress((void**)&colx,     g_col);
    cudaGetSymbolAddress((void**)&partials, g_partials);
    cudaGetSymbolAddress((void**)&dis,      g_dis);
    cudaGetSymbolAddress((void**)&ht,       g_ht);
    cudaGetSymbolAddress((void**)&a1s,      g_a1s);
    cudaGetSymbolAddress((void**)&h2,       g_h2);

    int nb    = (n + SCAN_CHUNK - 1) / SCAN_CHUNK;
    int nb_e2 = (e / 2 + 256) / 256;

    gemm_type_kernel<<<(nt + 63) / 64, 256>>>(emb, W1, ht, nt);

    cudaMemsetAsync(cnt, 0, (size_t)n * sizeof(int));
    count_kernel<<<nb_e2, 256>>>(dst, e, cnt);
    blocksum_kernel<<<nb, 256>>>(cnt, partials, n);
    scan_apply_kernel<<<nb, 256>>>(cnt, partials, rowptr, wptr, dis, n, nb);
    fill_kernel<<<nb_e2, 256>>>(src, dst, e, wptr, colx);

    int agg_blocks = (n + 7) / 8;

    agg1_fused_kernel<<<agg_blocks, 256>>>(ht, types, rowptr, colx, dis, b1, a1s, n);

    gemm2_tc_kernel<<<(n + 63) / 64, 256>>>(a1s, W2, h2, n);
    agg2_kernel<<<agg_blocks, 256>>>(h2, rowptr, colx, dis, b2, out, n);
}